// round 1
// baseline (speedup 1.0000x reference)
#include <cuda_runtime.h>
#include <math.h>

#define SS 2
#define NATOM 2048
#define CC 128
#define HH 8
#define DHD 16
#define CPD 16
#define TT 512
#define CTD 384
#define NBLK 3
#define WIN 128
#define NQB (NATOM/32)
#define EPS 1e-5f
#define SNC (SS*NATOM*CC)

#define EPI_NONE 0
#define EPI_SIG  1
#define EPI_SILU 2
#define EPI_RELU 3

// ---------------- scratch (device globals; no allocation allowed) ----------------
__device__ __align__(16) float g_sn  [NATOM*CC];
__device__ __align__(16) float g_sn2 [NATOM*CC];
__device__ __align__(16) float g_g1  [NATOM*CC];
__device__ __align__(16) float g_sh1 [NATOM*CC];
__device__ __align__(16) float g_og1 [NATOM*CC];
__device__ __align__(16) float g_g2  [NATOM*CC];
__device__ __align__(16) float g_sh2 [NATOM*CC];
__device__ __align__(16) float g_og2 [NATOM*CC];
__device__ __align__(16) float g_a   [SNC];
__device__ __align__(16) float g_a1  [SNC];
__device__ __align__(16) float g_q   [SNC];
__device__ __align__(16) float g_k   [SNC];
__device__ __align__(16) float g_v   [SNC];
__device__ __align__(16) float g_attg[SNC];
__device__ __align__(16) float g_o   [SNC];
__device__ __align__(16) float g_o2  [SNC];
__device__ __align__(16) float g_zb  [HH*NATOM*WIN];
__device__ __align__(16) float g_hid [SS*NATOM*2*CC];
__device__ __align__(16) float g_hid2[SS*NATOM*2*CC];
__device__ __align__(16) float g_qtok[SS*NATOM*CTD];
__device__ float g_cnt[TT];

// ---------------- helpers ----------------
__device__ __forceinline__ void blockReduce2_128(float& a, float& b) {
    // 128-thread block: sum a and b over all threads, result broadcast.
    #pragma unroll
    for (int o = 16; o; o >>= 1) {
        a += __shfl_xor_sync(0xffffffffu, a, o);
        b += __shfl_xor_sync(0xffffffffu, b, o);
    }
    __shared__ float sa[4], sb[4];
    int w = threadIdx.x >> 5;
    if ((threadIdx.x & 31) == 0) { sa[w] = a; sb[w] = b; }
    __syncthreads();
    a = sa[0] + sa[1] + sa[2] + sa[3];
    b = sb[0] + sb[1] + sb[2] + sb[3];
}

__device__ __forceinline__ float sigf(float x) { return 1.0f / (1.0f + __expf(-x)); }

// ---------------- kernels ----------------

// sn = LN(atom_proj; w1,b1), sn2 = LN(atom_proj; w2,b2). grid=NATOM, block=128
__global__ void k_ln_s(const float* __restrict__ ap,
                       const float* __restrict__ w1, const float* __restrict__ b1,
                       const float* __restrict__ w2, const float* __restrict__ b2) {
    int n = blockIdx.x, t = threadIdx.x;
    float x = ap[n * CC + t];
    float s1 = x, s2 = x * x;
    blockReduce2_128(s1, s2);
    float mu = s1 * (1.0f / CC);
    float var = s2 * (1.0f / CC) - mu * mu;
    float xn = (x - mu) * rsqrtf(var + EPS);
    g_sn [n * CC + t] = xn * w1[t] + b1[t];
    g_sn2[n * CC + t] = xn * w2[t] + b2[t];
}

// dst[s,n,:] = gate[n,:] * LN_noaffine(g_a[s,n,:]) + shift[n,:]. grid=(NATOM,SS), block=128
__global__ void k_mod(const float* __restrict__ gate, const float* __restrict__ shift,
                      float* __restrict__ dst) {
    int n = blockIdx.x, s = blockIdx.y, t = threadIdx.x;
    const float* row = g_a + (size_t)(s * NATOM + n) * CC;
    float x = row[t];
    float s1 = x, s2 = x * x;
    blockReduce2_128(s1, s2);
    float mu = s1 * (1.0f / CC);
    float var = s2 * (1.0f / CC) - mu * mu;
    float xn = (x - mu) * rsqrtf(var + EPS);
    dst[(size_t)(s * NATOM + n) * CC + t] = gate[n * CC + t] * xn + shift[n * CC + t];
}

// generic tiled SGEMM: Y[M,Ncol] = epi(X[M,K] @ W[K,Ncol] + bias)
// 64x64 tile, 256 threads, 4x4 per thread. M,Ncol multiples of 64; K multiple of 16.
__global__ void gemm64(const float* __restrict__ X, const float* __restrict__ Wm,
                       const float* __restrict__ bias, float* __restrict__ Y,
                       int M, int Ncol, int K, int epi) {
    __shared__ float As[16][68];
    __shared__ float Bs[16][64];
    int m0 = blockIdx.x * 64, n0 = blockIdx.y * 64;
    int tid = threadIdx.x;
    int tx = tid & 15, ty = tid >> 4;
    float acc[4][4] = {};
    for (int k0 = 0; k0 < K; k0 += 16) {
        {
            int mi = tid >> 2;
            int kk = (tid & 3) * 4;
            float4 v = *reinterpret_cast<const float4*>(X + (size_t)(m0 + mi) * K + k0 + kk);
            As[kk + 0][mi] = v.x; As[kk + 1][mi] = v.y;
            As[kk + 2][mi] = v.z; As[kk + 3][mi] = v.w;
        }
        {
            int kk = tid >> 4;
            int ni = (tid & 15) * 4;
            float4 v = *reinterpret_cast<const float4*>(Wm + (size_t)(k0 + kk) * Ncol + n0 + ni);
            *reinterpret_cast<float4*>(&Bs[kk][ni]) = v;
        }
        __syncthreads();
        #pragma unroll
        for (int kk = 0; kk < 16; kk++) {
            float a0 = As[kk][ty * 4 + 0], a1 = As[kk][ty * 4 + 1];
            float a2 = As[kk][ty * 4 + 2], a3 = As[kk][ty * 4 + 3];
            float b0 = Bs[kk][tx * 4 + 0], b1 = Bs[kk][tx * 4 + 1];
            float b2 = Bs[kk][tx * 4 + 2], b3 = Bs[kk][tx * 4 + 3];
            acc[0][0] += a0 * b0; acc[0][1] += a0 * b1; acc[0][2] += a0 * b2; acc[0][3] += a0 * b3;
            acc[1][0] += a1 * b0; acc[1][1] += a1 * b1; acc[1][2] += a1 * b2; acc[1][3] += a1 * b3;
            acc[2][0] += a2 * b0; acc[2][1] += a2 * b1; acc[2][2] += a2 * b2; acc[2][3] += a2 * b3;
            acc[3][0] += a3 * b0; acc[3][1] += a3 * b1; acc[3][2] += a3 * b2; acc[3][3] += a3 * b3;
        }
        __syncthreads();
    }
    #pragma unroll
    for (int i = 0; i < 4; i++) {
        int m = m0 + ty * 4 + i;
        #pragma unroll
        for (int j = 0; j < 4; j++) {
            int n = n0 + tx * 4 + j;
            float v = acc[i][j];
            if (bias) v += bias[n];
            if (epi == EPI_SIG)       v = sigf(v);
            else if (epi == EPI_SILU) v = v * sigf(v);
            else if (epi == EPI_RELU) v = fmaxf(v, 0.0f);
            Y[(size_t)m * Ncol + n] = v;
        }
    }
}

// pair bias for local windows: zb[h, q, w]. one thread per (q,w).
__global__ void k_zb(const float* __restrict__ pair, const float* __restrict__ lnw,
                     const float* __restrict__ lnb, const float* __restrict__ pw) {
    int idx = blockIdx.x * blockDim.x + threadIdx.x;
    if (idx >= NATOM * WIN) return;
    int q = idx >> 7, w = idx & 127;
    int m = (q >> 5) * 32 - 48 + w;
    float out[HH];
    #pragma unroll
    for (int h = 0; h < HH; h++) out[h] = 0.0f;
    if (m >= 0 && m < NATOM) {
        const float* p = pair + ((size_t)q * NATOM + m) * CPD;
        float v[CPD];
        float s1 = 0.0f, s2 = 0.0f;
        #pragma unroll
        for (int c = 0; c < CPD; c++) { v[c] = p[c]; s1 += v[c]; s2 += v[c] * v[c]; }
        float mu = s1 * (1.0f / CPD);
        float var = s2 * (1.0f / CPD) - mu * mu;
        float r = rsqrtf(var + EPS);
        #pragma unroll
        for (int c = 0; c < CPD; c++) {
            float xn = (v[c] - mu) * r * lnw[c] + lnb[c];
            #pragma unroll
            for (int h = 0; h < HH; h++) out[h] += xn * pw[c * HH + h];
        }
    }
    #pragma unroll
    for (int h = 0; h < HH; h++)
        g_zb[((size_t)h * NATOM + q) * WIN + w] = out[h];
}

// local attention: grid (NQB, H, S), block 128 (4 lanes per query, 32 queries).
__global__ void k_attn(const float* __restrict__ mask) {
    int qb = blockIdx.x, h = blockIdx.y, s = blockIdx.z;
    __shared__ float qs[32][DHD];
    __shared__ float ks[WIN][DHD];
    __shared__ float vs[WIN][DHD];
    __shared__ float mb[WIN];
    int tid = threadIdx.x;
    int kbase = qb * 32 - 48;
    for (int i = tid; i < 32 * DHD; i += 128) {
        int qi = i / DHD, d = i % DHD;
        qs[qi][d] = g_q[((size_t)s * NATOM + qb * 32 + qi) * CC + h * DHD + d] * 0.25f;
    }
    for (int i = tid; i < WIN * DHD; i += 128) {
        int j = i / DHD, d = i % DHD;
        int m = kbase + j;
        float kk = 0.0f, vv = 0.0f;
        if (m >= 0 && m < NATOM) {
            kk = g_k[((size_t)s * NATOM + m) * CC + h * DHD + d];
            vv = g_v[((size_t)s * NATOM + m) * CC + h * DHD + d];
        }
        ks[j][d] = kk; vs[j][d] = vv;
    }
    for (int j = tid; j < WIN; j += 128) {
        int m = kbase + j;
        mb[j] = (m >= 0 && m < NATOM) ? (mask[m] - 1.0f) * 1e8f : -1e30f;
    }
    __syncthreads();

    int qi = tid >> 2;
    int lane = tid & 3;
    int qg = qb * 32 + qi;
    const float* zrow = g_zb + ((size_t)h * NATOM + qg) * WIN;

    float lj[32];
    float mx = -1e30f;
    #pragma unroll
    for (int jj = 0; jj < 32; jj++) {
        int j = lane + jj * 4;
        float dot = 0.0f;
        #pragma unroll
        for (int d = 0; d < DHD; d++) dot += qs[qi][d] * ks[j][d];
        float l = dot + zrow[j] + mb[j];
        lj[jj] = l;
        mx = fmaxf(mx, l);
    }
    mx = fmaxf(mx, __shfl_xor_sync(0xffffffffu, mx, 1, 4));
    mx = fmaxf(mx, __shfl_xor_sync(0xffffffffu, mx, 2, 4));

    float sum = 0.0f;
    float oacc[DHD];
    #pragma unroll
    for (int d = 0; d < DHD; d++) oacc[d] = 0.0f;
    #pragma unroll
    for (int jj = 0; jj < 32; jj++) {
        int j = lane + jj * 4;
        float p = __expf(lj[jj] - mx);
        sum += p;
        #pragma unroll
        for (int d = 0; d < DHD; d++) oacc[d] += p * vs[j][d];
    }
    sum += __shfl_xor_sync(0xffffffffu, sum, 1, 4);
    sum += __shfl_xor_sync(0xffffffffu, sum, 2, 4);
    #pragma unroll
    for (int d = 0; d < DHD; d++) {
        oacc[d] += __shfl_xor_sync(0xffffffffu, oacc[d], 1, 4);
        oacc[d] += __shfl_xor_sync(0xffffffffu, oacc[d], 2, 4);
    }
    if (lane == 0) {
        float inv = 1.0f / sum;
        #pragma unroll
        for (int d = 0; d < DHD; d++)
            g_o[((size_t)s * NATOM + qg) * CC + h * DHD + d] = oacc[d] * inv;
    }
}

__global__ void k_init_a(const float* __restrict__ src) {
    int i = blockIdx.x * blockDim.x + threadIdx.x;
    if (i < SNC) g_a[i] = src[i];
}

__global__ void k_mul(float* __restrict__ x, const float* __restrict__ y, int n) {
    int i = blockIdx.x * blockDim.x + threadIdx.x;
    if (i < n) x[i] *= y[i];
}

// a[s,n,c] += og[n,c] * o2[s,n,c]
__global__ void k_update_a(const float* __restrict__ og, const float* __restrict__ o2) {
    int i = blockIdx.x * blockDim.x + threadIdx.x;
    if (i < SNC) {
        int nc = i % (NATOM * CC);
        g_a[i] += og[nc] * o2[i];
    }
}

__global__ void k_zero_out(float* __restrict__ out) {
    int i = blockIdx.x * blockDim.x + threadIdx.x;
    if (i < SS * TT * CTD) out[i] = 0.0f;
    if (i < TT) g_cnt[i] = 0.0f;
}

__global__ void k_count(const int* __restrict__ tok) {
    int n = blockIdx.x * blockDim.x + threadIdx.x;
    if (n < NATOM) atomicAdd(&g_cnt[tok[n]], 1.0f);
}

__global__ void k_invcnt() {
    int t = blockIdx.x * blockDim.x + threadIdx.x;
    if (t < TT) g_cnt[t] = 1.0f / fmaxf(g_cnt[t], 1.0f);
}

__global__ void k_scatter(const int* __restrict__ tok, float* __restrict__ out) {
    int i = blockIdx.x * blockDim.x + threadIdx.x;
    if (i >= SS * NATOM * CTD) return;
    int c = i % CTD;
    int n = (i / CTD) % NATOM;
    int s = i / (CTD * NATOM);
    int t = tok[n];
    atomicAdd(&out[((size_t)s * TT + t) * CTD + c], g_qtok[i] * g_cnt[t]);
}

// ---------------- host ----------------
extern "C" void kernel_launch(void* const* d_in, const int* in_sizes, int n_in,
                              void* d_out, int out_size) {
    const float* atom_single = (const float*)d_in[0];
    const float* atom_proj   = (const float*)d_in[1];
    const float* atom_pair   = (const float*)d_in[2];
    const float* mask        = (const float*)d_in[3];
    const int*   tok_idx     = (const int*)  d_in[4];
    const float* aln_s_w     = (const float*)d_in[5];
    const float* aln_s_b     = (const float*)d_in[6];
    const float* aln_gate_w  = (const float*)d_in[7];
    const float* aln_gate_b  = (const float*)d_in[8];
    const float* aln_shift_w = (const float*)d_in[9];
    const float* q_w         = (const float*)d_in[10];
    const float* q_b         = (const float*)d_in[11];
    const float* k_w         = (const float*)d_in[12];
    const float* v_w         = (const float*)d_in[13];
    const float* pair_ln_w   = (const float*)d_in[14];
    const float* pair_ln_b   = (const float*)d_in[15];
    const float* pair_w      = (const float*)d_in[16];
    const float* gate_w      = (const float*)d_in[17];
    const float* out_w       = (const float*)d_in[18];
    const float* og_w        = (const float*)d_in[19];
    const float* og_b        = (const float*)d_in[20];
    const float* t_aln_s_w   = (const float*)d_in[21];
    const float* t_aln_s_b   = (const float*)d_in[22];
    const float* t_aln_gate_w= (const float*)d_in[23];
    const float* t_aln_gate_b= (const float*)d_in[24];
    const float* t_aln_shift_w=(const float*)d_in[25];
    const float* t_a_w       = (const float*)d_in[26];
    const float* t_b_w       = (const float*)d_in[27];
    const float* t_out_w     = (const float*)d_in[28];
    const float* t_og_w      = (const float*)d_in[29];
    const float* t_og_b      = (const float*)d_in[30];
    const float* tok_w       = (const float*)d_in[31];
    float* out = (float*)d_out;

    static float *p_sn=0,*p_sn2=0,*p_g1=0,*p_sh1=0,*p_og1=0,*p_g2=0,*p_sh2=0,*p_og2=0;
    static float *p_a1=0,*p_q=0,*p_k=0,*p_v=0,*p_attg=0,*p_o=0,*p_o2=0;
    static float *p_a=0,*p_hid=0,*p_hid2=0,*p_qtok=0;
    if (!p_sn) {
        cudaGetSymbolAddress((void**)&p_sn,   g_sn);
        cudaGetSymbolAddress((void**)&p_sn2,  g_sn2);
        cudaGetSymbolAddress((void**)&p_g1,   g_g1);
        cudaGetSymbolAddress((void**)&p_sh1,  g_sh1);
        cudaGetSymbolAddress((void**)&p_og1,  g_og1);
        cudaGetSymbolAddress((void**)&p_g2,   g_g2);
        cudaGetSymbolAddress((void**)&p_sh2,  g_sh2);
        cudaGetSymbolAddress((void**)&p_og2,  g_og2);
        cudaGetSymbolAddress((void**)&p_a,    g_a);
        cudaGetSymbolAddress((void**)&p_a1,   g_a1);
        cudaGetSymbolAddress((void**)&p_q,    g_q);
        cudaGetSymbolAddress((void**)&p_k,    g_k);
        cudaGetSymbolAddress((void**)&p_v,    g_v);
        cudaGetSymbolAddress((void**)&p_attg, g_attg);
        cudaGetSymbolAddress((void**)&p_o,    g_o);
        cudaGetSymbolAddress((void**)&p_o2,   g_o2);
        cudaGetSymbolAddress((void**)&p_hid,  g_hid);
        cudaGetSymbolAddress((void**)&p_hid2, g_hid2);
        cudaGetSymbolAddress((void**)&p_qtok, g_qtok);
    }

    const int M1 = NATOM;        // per-atom (s-broadcast) rows
    const int M2 = SS * NATOM;   // per-(s,atom) rows

    k_init_a<<<(SNC + 255) / 256, 256>>>(atom_single);

    for (int i = 0; i < NBLK; i++) {
        const float* gw  = aln_gate_w  + (size_t)i * CC * CC;
        const float* gb  = aln_gate_b  + (size_t)i * CC;
        const float* shw = aln_shift_w + (size_t)i * CC * CC;
        const float* qwi = q_w  + (size_t)i * CC * CC;
        const float* qbi = q_b  + (size_t)i * CC;
        const float* kwi = k_w  + (size_t)i * CC * CC;
        const float* vwi = v_w  + (size_t)i * CC * CC;
        const float* gtw = gate_w + (size_t)i * CC * CC;
        const float* otw = out_w  + (size_t)i * CC * CC;
        const float* ogw = og_w   + (size_t)i * CC * CC;
        const float* ogb = og_b   + (size_t)i * CC;
        const float* tgw = t_aln_gate_w  + (size_t)i * CC * CC;
        const float* tgb = t_aln_gate_b  + (size_t)i * CC;
        const float* tsw = t_aln_shift_w + (size_t)i * CC * CC;
        const float* taw = t_a_w   + (size_t)i * CC * 2 * CC;
        const float* tbw = t_b_w   + (size_t)i * CC * 2 * CC;
        const float* tow = t_out_w + (size_t)i * 2 * CC * CC;
        const float* togw= t_og_w  + (size_t)i * CC * CC;
        const float* togb= t_og_b  + (size_t)i * CC;

        // LN of s with both param sets
        k_ln_s<<<NATOM, 128>>>(atom_proj,
                               aln_s_w + (size_t)i * CC,  aln_s_b + (size_t)i * CC,
                               t_aln_s_w + (size_t)i * CC, t_aln_s_b + (size_t)i * CC);

        // sn projections
        gemm64<<<dim3(M1/64, CC/64), 256>>>(p_sn,  gw,  gb,  p_g1,  M1, CC, CC, EPI_SIG);
        gemm64<<<dim3(M1/64, CC/64), 256>>>(p_sn,  shw, 0,   p_sh1, M1, CC, CC, EPI_NONE);
        gemm64<<<dim3(M1/64, CC/64), 256>>>(p_sn,  ogw, ogb, p_og1, M1, CC, CC, EPI_SIG);
        gemm64<<<dim3(M1/64, CC/64), 256>>>(p_sn2, tgw, tgb, p_g2,  M1, CC, CC, EPI_SIG);
        gemm64<<<dim3(M1/64, CC/64), 256>>>(p_sn2, tsw, 0,   p_sh2, M1, CC, CC, EPI_NONE);
        gemm64<<<dim3(M1/64, CC/64), 256>>>(p_sn2, togw,togb,p_og2, M1, CC, CC, EPI_SIG);

        // a1 = gate1 * LN_na(a) + shift1
        k_mod<<<dim3(NATOM, SS), 128>>>(p_g1, p_sh1, p_a1);

        // q,k,v
        gemm64<<<dim3(M2/64, CC/64), 256>>>(p_a1, qwi, qbi, p_q, M2, CC, CC, EPI_NONE);
        gemm64<<<dim3(M2/64, CC/64), 256>>>(p_a1, kwi, 0,   p_k, M2, CC, CC, EPI_NONE);
        gemm64<<<dim3(M2/64, CC/64), 256>>>(p_a1, vwi, 0,   p_v, M2, CC, CC, EPI_NONE);

        // pair bias (local windows only)
        k_zb<<<(NATOM * WIN + 255) / 256, 256>>>(atom_pair,
                                                 pair_ln_w + (size_t)i * CPD,
                                                 pair_ln_b + (size_t)i * CPD,
                                                 pair_w + (size_t)i * CPD * HH);

        // attention
        k_attn<<<dim3(NQB, HH, SS), 128>>>(mask);

        // gated output projection + residual
        gemm64<<<dim3(M2/64, CC/64), 256>>>(p_a1, gtw, 0, p_attg, M2, CC, CC, EPI_SIG);
        k_mul<<<(SNC + 255) / 256, 256>>>(p_o, p_attg, SNC);
        gemm64<<<dim3(M2/64, CC/64), 256>>>(p_o, otw, 0, p_o2, M2, CC, CC, EPI_NONE);
        k_update_a<<<(SNC + 255) / 256, 256>>>(p_og1, p_o2);

        // transition: a2 = gate2 * LN_na(a) + shift2 (reuse g_a1)
        k_mod<<<dim3(NATOM, SS), 128>>>(p_g2, p_sh2, p_a1);
        gemm64<<<dim3(M2/64, (2*CC)/64), 256>>>(p_a1, taw, 0, p_hid,  M2, 2*CC, CC, EPI_SILU);
        gemm64<<<dim3(M2/64, (2*CC)/64), 256>>>(p_a1, tbw, 0, p_hid2, M2, 2*CC, CC, EPI_NONE);
        k_mul<<<(SS*NATOM*2*CC + 255) / 256, 256>>>(p_hid, p_hid2, SS*NATOM*2*CC);
        gemm64<<<dim3(M2/64, CC/64), 256>>>(p_hid, tow, 0, p_o2, M2, CC, 2*CC, EPI_NONE);
        k_update_a<<<(SNC + 255) / 256, 256>>>(p_og2, p_o2);
    }

    // token head
    gemm64<<<dim3(M2/64, CTD/64), 256>>>(p_a, tok_w, 0, p_qtok, M2, CTD, CC, EPI_RELU);
    k_zero_out<<<(SS * TT * CTD + 255) / 256, 256>>>(out);
    k_count<<<(NATOM + 255) / 256, 256>>>(tok_idx);
    k_invcnt<<<(TT + 255) / 256, 256>>>();
    k_scatter<<<(SS * NATOM * CTD + 255) / 256, 256>>>(tok_idx, out);
}

// round 6
// speedup vs baseline: 1.5021x; 1.5021x over previous
#include <cuda_runtime.h>
#include <math.h>

#define SS 2
#define NATOM 2048
#define CC 128
#define HH 8
#define DHD 16
#define CPD 16
#define TT 512
#define CTD 384
#define NBLK 3
#define WIN 128
#define NQB (NATOM/32)
#define EPS 1e-5f
#define SNC (SS*NATOM*CC)

#define EPI_NONE 0
#define EPI_SIG  1
#define EPI_RELU 3

// ---------------- scratch ----------------
__device__ __align__(16) float g_sn  [NATOM*CC];
__device__ __align__(16) float g_sn2 [NATOM*CC];
__device__ __align__(16) float g_g1  [NATOM*CC];
__device__ __align__(16) float g_sh1 [NATOM*CC];
__device__ __align__(16) float g_og1 [NATOM*CC];
__device__ __align__(16) float g_g2  [NATOM*CC];
__device__ __align__(16) float g_sh2 [NATOM*CC];
__device__ __align__(16) float g_og2 [NATOM*CC];
__device__ __align__(16) float g_a   [SNC];
__device__ __align__(16) float g_a1  [SNC];
__device__ __align__(16) float g_q   [SNC];
__device__ __align__(16) float g_k   [SNC];
__device__ __align__(16) float g_v   [SNC];
__device__ __align__(16) float g_attg[SNC];
__device__ __align__(16) float g_o   [SNC];
__device__ __align__(16) float g_zb  [HH*NATOM*WIN];
__device__ __align__(16) float g_hid [SS*NATOM*2*CC];
__device__ __align__(16) float g_qtok[SS*NATOM*CTD];
__device__ float g_cnt[TT];

// ---------------- helpers ----------------
__device__ __forceinline__ void blockReduce2_128(float& a, float& b) {
    #pragma unroll
    for (int o = 16; o; o >>= 1) {
        a += __shfl_xor_sync(0xffffffffu, a, o);
        b += __shfl_xor_sync(0xffffffffu, b, o);
    }
    __shared__ float sa[4], sb[4];
    int w = threadIdx.x >> 5;
    if ((threadIdx.x & 31) == 0) { sa[w] = a; sb[w] = b; }
    __syncthreads();
    a = sa[0] + sa[1] + sa[2] + sa[3];
    b = sb[0] + sb[1] + sb[2] + sb[3];
}

__device__ __forceinline__ float sigf(float x) { return 1.0f / (1.0f + __expf(-x)); }

// ---------------- LN kernels ----------------
__global__ void k_ln_s(const float* __restrict__ ap,
                       const float* __restrict__ w1, const float* __restrict__ b1,
                       const float* __restrict__ w2, const float* __restrict__ b2) {
    int n = blockIdx.x, t = threadIdx.x;
    float x = ap[n * CC + t];
    float s1 = x, s2 = x * x;
    blockReduce2_128(s1, s2);
    float mu = s1 * (1.0f / CC);
    float var = s2 * (1.0f / CC) - mu * mu;
    float xn = (x - mu) * rsqrtf(var + EPS);
    g_sn [n * CC + t] = xn * w1[t] + b1[t];
    g_sn2[n * CC + t] = xn * w2[t] + b2[t];
}

__global__ void k_mod(const float* __restrict__ gate, const float* __restrict__ shift,
                      float* __restrict__ dst) {
    int n = blockIdx.x, s = blockIdx.y, t = threadIdx.x;
    float x = g_a[(size_t)(s * NATOM + n) * CC + t];
    float s1 = x, s2 = x * x;
    blockReduce2_128(s1, s2);
    float mu = s1 * (1.0f / CC);
    float var = s2 * (1.0f / CC) - mu * mu;
    float xn = (x - mu) * rsqrtf(var + EPS);
    dst[(size_t)(s * NATOM + n) * CC + t] = gate[n * CC + t] * xn + shift[n * CC + t];
}

// ---------------- GEMM core (64x64 tile, 256 thr, 4x4/thread) ----------------
struct GB {
    const float* X[6];
    const float* W[6];
    const float* B[6];
    float*       Y[6];
    int          epi[6];
};

__device__ __forceinline__ void gemm_tile_loop(const float* __restrict__ X,
                                               const float* __restrict__ Wm,
                                               int m0, int n0, int K, int Ncol,
                                               float (&As)[16][68], float (&Bs)[16][64],
                                               float (&acc)[4][4]) {
    int tid = threadIdx.x;
    int tx = tid & 15, ty = tid >> 4;
    for (int k0 = 0; k0 < K; k0 += 16) {
        {
            int mi = tid >> 2;
            int kk = (tid & 3) * 4;
            float4 v = *reinterpret_cast<const float4*>(X + (size_t)(m0 + mi) * K + k0 + kk);
            As[kk + 0][mi] = v.x; As[kk + 1][mi] = v.y;
            As[kk + 2][mi] = v.z; As[kk + 3][mi] = v.w;
        }
        {
            int kk = tid >> 4;
            int ni = (tid & 15) * 4;
            float4 v = *reinterpret_cast<const float4*>(Wm + (size_t)(k0 + kk) * Ncol + n0 + ni);
            *reinterpret_cast<float4*>(&Bs[kk][ni]) = v;
        }
        __syncthreads();
        #pragma unroll
        for (int kk = 0; kk < 16; kk++) {
            float a0 = As[kk][ty * 4 + 0], a1 = As[kk][ty * 4 + 1];
            float a2 = As[kk][ty * 4 + 2], a3 = As[kk][ty * 4 + 3];
            float b0 = Bs[kk][tx * 4 + 0], b1 = Bs[kk][tx * 4 + 1];
            float b2 = Bs[kk][tx * 4 + 2], b3 = Bs[kk][tx * 4 + 3];
            acc[0][0] += a0 * b0; acc[0][1] += a0 * b1; acc[0][2] += a0 * b2; acc[0][3] += a0 * b3;
            acc[1][0] += a1 * b0; acc[1][1] += a1 * b1; acc[1][2] += a1 * b2; acc[1][3] += a1 * b3;
            acc[2][0] += a2 * b0; acc[2][1] += a2 * b1; acc[2][2] += a2 * b2; acc[2][3] += a2 * b3;
            acc[3][0] += a3 * b0; acc[3][1] += a3 * b1; acc[3][2] += a3 * b2; acc[3][3] += a3 * b3;
        }
        __syncthreads();
    }
}

// batched gemm: z picks (X,W,B,Y,epi); all share M,Ncol,K.
__global__ void gemm64b(GB gb, int Ncol, int K) {
    __shared__ float As[16][68];
    __shared__ float Bs[16][64];
    int z = blockIdx.z;
    int m0 = blockIdx.x * 64, n0 = blockIdx.y * 64;
    float acc[4][4] = {};
    gemm_tile_loop(gb.X[z], gb.W[z], m0, n0, K, Ncol, As, Bs, acc);
    const float* bias = gb.B[z];
    float* Y = gb.Y[z];
    int epi = gb.epi[z];
    int tid = threadIdx.x;
    int tx = tid & 15, ty = tid >> 4;
    #pragma unroll
    for (int i = 0; i < 4; i++) {
        int m = m0 + ty * 4 + i;
        #pragma unroll
        for (int j = 0; j < 4; j++) {
            int n = n0 + tx * 4 + j;
            float v = acc[i][j];
            if (bias) v += bias[n];
            if (epi == EPI_SIG)       v = sigf(v);
            else if (epi == EPI_RELU) v = fmaxf(v, 0.0f);
            Y[(size_t)m * Ncol + n] = v;
        }
    }
}

// gated out-proj: X = attg * o (on the fly), Y: a += og1 * (X @ W). M=SS*NATOM,N=128,K=128
__global__ void gemm_gateout(const float* __restrict__ attg, const float* __restrict__ o,
                             const float* __restrict__ Wm, const float* __restrict__ og) {
    __shared__ float As[16][68];
    __shared__ float Bs[16][64];
    int m0 = blockIdx.x * 64, n0 = blockIdx.y * 64;
    int tid = threadIdx.x;
    int tx = tid & 15, ty = tid >> 4;
    float acc[4][4] = {};
    for (int k0 = 0; k0 < CC; k0 += 16) {
        {
            int mi = tid >> 2;
            int kk = (tid & 3) * 4;
            size_t off = (size_t)(m0 + mi) * CC + k0 + kk;
            float4 g = *reinterpret_cast<const float4*>(attg + off);
            float4 v = *reinterpret_cast<const float4*>(o + off);
            As[kk + 0][mi] = g.x * v.x; As[kk + 1][mi] = g.y * v.y;
            As[kk + 2][mi] = g.z * v.z; As[kk + 3][mi] = g.w * v.w;
        }
        {
            int kk = tid >> 4;
            int ni = (tid & 15) * 4;
            float4 v = *reinterpret_cast<const float4*>(Wm + (size_t)(k0 + kk) * CC + n0 + ni);
            *reinterpret_cast<float4*>(&Bs[kk][ni]) = v;
        }
        __syncthreads();
        #pragma unroll
        for (int kk = 0; kk < 16; kk++) {
            float a0 = As[kk][ty * 4 + 0], a1 = As[kk][ty * 4 + 1];
            float a2 = As[kk][ty * 4 + 2], a3 = As[kk][ty * 4 + 3];
            float b0 = Bs[kk][tx * 4 + 0], b1 = Bs[kk][tx * 4 + 1];
            float b2 = Bs[kk][tx * 4 + 2], b3 = Bs[kk][tx * 4 + 3];
            acc[0][0] += a0 * b0; acc[0][1] += a0 * b1; acc[0][2] += a0 * b2; acc[0][3] += a0 * b3;
            acc[1][0] += a1 * b0; acc[1][1] += a1 * b1; acc[1][2] += a1 * b2; acc[1][3] += a1 * b3;
            acc[2][0] += a2 * b0; acc[2][1] += a2 * b1; acc[2][2] += a2 * b2; acc[2][3] += a2 * b3;
            acc[3][0] += a3 * b0; acc[3][1] += a3 * b1; acc[3][2] += a3 * b2; acc[3][3] += a3 * b3;
        }
        __syncthreads();
    }
    #pragma unroll
    for (int i = 0; i < 4; i++) {
        int m = m0 + ty * 4 + i;
        int natom_c = (m & (NATOM - 1)) * CC;
        #pragma unroll
        for (int j = 0; j < 4; j++) {
            int n = n0 + tx * 4 + j;
            g_a[(size_t)m * CC + n] += og[natom_c + n] * acc[i][j];
        }
    }
}

// transition dual gemm: hid = silu(a1 @ Wa) * (a1 @ Wb). N=256, K=128.
__global__ void gemm_dual(const float* __restrict__ X, const float* __restrict__ Wa,
                          const float* __restrict__ Wb) {
    __shared__ float As[16][68];
    __shared__ float Bs[2][16][64];
    const int N2 = 2 * CC;
    int m0 = blockIdx.x * 64, n0 = blockIdx.y * 64;
    int tid = threadIdx.x;
    int tx = tid & 15, ty = tid >> 4;
    float acc[2][4][4] = {};
    for (int k0 = 0; k0 < CC; k0 += 16) {
        {
            int mi = tid >> 2;
            int kk = (tid & 3) * 4;
            float4 v = *reinterpret_cast<const float4*>(X + (size_t)(m0 + mi) * CC + k0 + kk);
            As[kk + 0][mi] = v.x; As[kk + 1][mi] = v.y;
            As[kk + 2][mi] = v.z; As[kk + 3][mi] = v.w;
        }
        {
            int kk = tid >> 4;
            int ni = (tid & 15) * 4;
            float4 va = *reinterpret_cast<const float4*>(Wa + (size_t)(k0 + kk) * N2 + n0 + ni);
            float4 vb = *reinterpret_cast<const float4*>(Wb + (size_t)(k0 + kk) * N2 + n0 + ni);
            *reinterpret_cast<float4*>(&Bs[0][kk][ni]) = va;
            *reinterpret_cast<float4*>(&Bs[1][kk][ni]) = vb;
        }
        __syncthreads();
        #pragma unroll
        for (int kk = 0; kk < 16; kk++) {
            float a0 = As[kk][ty * 4 + 0], a1 = As[kk][ty * 4 + 1];
            float a2 = As[kk][ty * 4 + 2], a3 = As[kk][ty * 4 + 3];
            #pragma unroll
            for (int w = 0; w < 2; w++) {
                float b0 = Bs[w][kk][tx * 4 + 0], b1 = Bs[w][kk][tx * 4 + 1];
                float b2 = Bs[w][kk][tx * 4 + 2], b3 = Bs[w][kk][tx * 4 + 3];
                acc[w][0][0] += a0 * b0; acc[w][0][1] += a0 * b1; acc[w][0][2] += a0 * b2; acc[w][0][3] += a0 * b3;
                acc[w][1][0] += a1 * b0; acc[w][1][1] += a1 * b1; acc[w][1][2] += a1 * b2; acc[w][1][3] += a1 * b3;
                acc[w][2][0] += a2 * b0; acc[w][2][1] += a2 * b1; acc[w][2][2] += a2 * b2; acc[w][2][3] += a2 * b3;
                acc[w][3][0] += a3 * b0; acc[w][3][1] += a3 * b1; acc[w][3][2] += a3 * b2; acc[w][3][3] += a3 * b3;
            }
        }
        __syncthreads();
    }
    #pragma unroll
    for (int i = 0; i < 4; i++) {
        int m = m0 + ty * 4 + i;
        #pragma unroll
        for (int j = 0; j < 4; j++) {
            int n = n0 + tx * 4 + j;
            float h = acc[0][i][j];
            g_hid[(size_t)m * N2 + n] = h * sigf(h) * acc[1][i][j];
        }
    }
}

// t_out gemm: a += og2 * (hid @ W). K=256, N=128.
__global__ void gemm_tout(const float* __restrict__ Wm, const float* __restrict__ og) {
    __shared__ float As[16][68];
    __shared__ float Bs[16][64];
    const int K = 2 * CC;
    int m0 = blockIdx.x * 64, n0 = blockIdx.y * 64;
    float acc[4][4] = {};
    gemm_tile_loop(g_hid, Wm, m0, n0, K, CC, As, Bs, acc);
    int tid = threadIdx.x;
    int tx = tid & 15, ty = tid >> 4;
    #pragma unroll
    for (int i = 0; i < 4; i++) {
        int m = m0 + ty * 4 + i;
        int natom_c = (m & (NATOM - 1)) * CC;
        #pragma unroll
        for (int j = 0; j < 4; j++) {
            int n = n0 + tx * 4 + j;
            g_a[(size_t)m * CC + n] += og[natom_c + n] * acc[i][j];
        }
    }
}

// token head gemm (relu epilogue): qtok = relu(a @ tok_w). N=384, K=128.
__global__ void gemm_tok(const float* __restrict__ Wm) {
    __shared__ float As[16][68];
    __shared__ float Bs[16][64];
    int m0 = blockIdx.x * 64, n0 = blockIdx.y * 64;
    float acc[4][4] = {};
    gemm_tile_loop(g_a, Wm, m0, n0, CC, CTD, As, Bs, acc);
    int tid = threadIdx.x;
    int tx = tid & 15, ty = tid >> 4;
    #pragma unroll
    for (int i = 0; i < 4; i++) {
        int m = m0 + ty * 4 + i;
        #pragma unroll
        for (int j = 0; j < 4; j++) {
            int n = n0 + tx * 4 + j;
            g_qtok[(size_t)m * CTD + n] = fmaxf(acc[i][j], 0.0f);
        }
    }
}

// ---------------- pair bias ----------------
__global__ void k_zb(const float* __restrict__ pair, const float* __restrict__ lnw,
                     const float* __restrict__ lnb, const float* __restrict__ pw) {
    int idx = blockIdx.x * blockDim.x + threadIdx.x;
    if (idx >= NATOM * WIN) return;
    int q = idx >> 7, w = idx & 127;
    int m = (q >> 5) * 32 - 48 + w;
    float out[HH];
    #pragma unroll
    for (int h = 0; h < HH; h++) out[h] = 0.0f;
    if (m >= 0 && m < NATOM) {
        const float* p = pair + ((size_t)q * NATOM + m) * CPD;
        float v[CPD];
        float s1 = 0.0f, s2 = 0.0f;
        #pragma unroll
        for (int c = 0; c < CPD; c++) { v[c] = p[c]; s1 += v[c]; s2 += v[c] * v[c]; }
        float mu = s1 * (1.0f / CPD);
        float var = s2 * (1.0f / CPD) - mu * mu;
        float r = rsqrtf(var + EPS);
        #pragma unroll
        for (int c = 0; c < CPD; c++) {
            float xn = (v[c] - mu) * r * lnw[c] + lnb[c];
            #pragma unroll
            for (int h = 0; h < HH; h++) out[h] += xn * pw[c * HH + h];
        }
    }
    #pragma unroll
    for (int h = 0; h < HH; h++)
        g_zb[((size_t)h * NATOM + q) * WIN + w] = out[h];
}

// ---------------- local attention ----------------
__global__ void k_attn(const float* __restrict__ mask) {
    int qb = blockIdx.x, h = blockIdx.y, s = blockIdx.z;
    __shared__ float qs[32][DHD];
    __shared__ float ks[WIN][DHD];
    __shared__ float vs[WIN][DHD];
    __shared__ float mb[WIN];
    int tid = threadIdx.x;
    int kbase = qb * 32 - 48;
    for (int i = tid; i < 32 * DHD; i += 128) {
        int qi = i / DHD, d = i % DHD;
        qs[qi][d] = g_q[((size_t)s * NATOM + qb * 32 + qi) * CC + h * DHD + d] * 0.25f;
    }
    for (int i = tid; i < WIN * DHD; i += 128) {
        int j = i / DHD, d = i % DHD;
        int m = kbase + j;
        float kk = 0.0f, vv = 0.0f;
        if (m >= 0 && m < NATOM) {
            kk = g_k[((size_t)s * NATOM + m) * CC + h * DHD + d];
            vv = g_v[((size_t)s * NATOM + m) * CC + h * DHD + d];
        }
        ks[j][d] = kk; vs[j][d] = vv;
    }
    for (int j = tid; j < WIN; j += 128) {
        int m = kbase + j;
        mb[j] = (m >= 0 && m < NATOM) ? (mask[m] - 1.0f) * 1e8f : -1e30f;
    }
    __syncthreads();

    int qi = tid >> 2;
    int lane = tid & 3;
    int qg = qb * 32 + qi;
    const float* zrow = g_zb + ((size_t)h * NATOM + qg) * WIN;

    float lj[32];
    float mx = -1e30f;
    #pragma unroll
    for (int jj = 0; jj < 32; jj++) {
        int j = lane + jj * 4;
        float dot = 0.0f;
        #pragma unroll
        for (int d = 0; d < DHD; d++) dot += qs[qi][d] * ks[j][d];
        float l = dot + zrow[j] + mb[j];
        lj[jj] = l;
        mx = fmaxf(mx, l);
    }
    mx = fmaxf(mx, __shfl_xor_sync(0xffffffffu, mx, 1, 4));
    mx = fmaxf(mx, __shfl_xor_sync(0xffffffffu, mx, 2, 4));

    float sum = 0.0f;
    float oacc[DHD];
    #pragma unroll
    for (int d = 0; d < DHD; d++) oacc[d] = 0.0f;
    #pragma unroll
    for (int jj = 0; jj < 32; jj++) {
        int j = lane + jj * 4;
        float p = __expf(lj[jj] - mx);
        sum += p;
        #pragma unroll
        for (int d = 0; d < DHD; d++) oacc[d] += p * vs[j][d];
    }
    sum += __shfl_xor_sync(0xffffffffu, sum, 1, 4);
    sum += __shfl_xor_sync(0xffffffffu, sum, 2, 4);
    #pragma unroll
    for (int d = 0; d < DHD; d++) {
        oacc[d] += __shfl_xor_sync(0xffffffffu, oacc[d], 1, 4);
        oacc[d] += __shfl_xor_sync(0xffffffffu, oacc[d], 2, 4);
    }
    if (lane == 0) {
        float inv = 1.0f / sum;
        #pragma unroll
        for (int d = 0; d < DHD; d++)
            g_o[((size_t)s * NATOM + qg) * CC + h * DHD + d] = oacc[d] * inv;
    }
}

// ---------------- small kernels ----------------
__global__ void k_init_a(const float* __restrict__ src) {
    int i = blockIdx.x * blockDim.x + threadIdx.x;
    if (i < SNC) g_a[i] = src[i];
}

__global__ void k_zero_out(float* __restrict__ out) {
    int i = blockIdx.x * blockDim.x + threadIdx.x;
    if (i < SS * TT * CTD) out[i] = 0.0f;
    if (i < TT) g_cnt[i] = 0.0f;
}

__global__ void k_count(const int* __restrict__ tok) {
    int n = blockIdx.x * blockDim.x + threadIdx.x;
    if (n < NATOM) atomicAdd(&g_cnt[tok[n]], 1.0f);
}

__global__ void k_invcnt() {
    int t = blockIdx.x * blockDim.x + threadIdx.x;
    if (t < TT) g_cnt[t] = 1.0f / fmaxf(g_cnt[t], 1.0f);
}

__global__ void k_scatter(const int* __restrict__ tok, float* __restrict__ out) {
    int i = blockIdx.x * blockDim.x + threadIdx.x;
    if (i >= SS * NATOM * CTD) return;
    int c = i % CTD;
    int n = (i / CTD) % NATOM;
    int s = i / (CTD * NATOM);
    int t = tok[n];
    atomicAdd(&out[((size_t)s * TT + t) * CTD + c], g_qtok[i] * g_cnt[t]);
}

// ---------------- host ----------------
extern "C" void kernel_launch(void* const* d_in, const int* in_sizes, int n_in,
                              void* d_out, int out_size) {
    const float* atom_single = (const float*)d_in[0];
    const float* atom_proj   = (const float*)d_in[1];
    const float* atom_pair   = (const float*)d_in[2];
    const float* mask        = (const float*)d_in[3];
    const int*   tok_idx     = (const int*)  d_in[4];
    const float* aln_s_w     = (const float*)d_in[5];
    const float* aln_s_b     = (const float*)d_in[6];
    const float* aln_gate_w  = (const float*)d_in[7];
    const float* aln_gate_b  = (const float*)d_in[8];
    const float* aln_shift_w = (const float*)d_in[9];
    const float* q_w         = (const float*)d_in[10];
    const float* q_b         = (const float*)d_in[11];
    const float* k_w         = (const float*)d_in[12];
    const float* v_w         = (const float*)d_in[13];
    const float* pair_ln_w   = (const float*)d_in[14];
    const float* pair_ln_b   = (const float*)d_in[15];
    const float* pair_w      = (const float*)d_in[16];
    const float* gate_w      = (const float*)d_in[17];
    const float* out_w       = (const float*)d_in[18];
    const float* og_w        = (const float*)d_in[19];
    const float* og_b        = (const float*)d_in[20];
    const float* t_aln_s_w   = (const float*)d_in[21];
    const float* t_aln_s_b   = (const float*)d_in[22];
    const float* t_aln_gate_w= (const float*)d_in[23];
    const float* t_aln_gate_b= (const float*)d_in[24];
    const float* t_aln_shift_w=(const float*)d_in[25];
    const float* t_a_w       = (const float*)d_in[26];
    const float* t_b_w       = (const float*)d_in[27];
    const float* t_out_w     = (const float*)d_in[28];
    const float* t_og_w      = (const float*)d_in[29];
    const float* t_og_b      = (const float*)d_in[30];
    const float* tok_w       = (const float*)d_in[31];
    float* out = (float*)d_out;

    static float *p_sn=0,*p_sn2=0,*p_g1=0,*p_sh1=0,*p_og1=0,*p_g2=0,*p_sh2=0,*p_og2=0;
    static float *p_a1=0,*p_q=0,*p_k=0,*p_v=0,*p_attg=0,*p_o=0;
    if (!p_sn) {
        cudaGetSymbolAddress((void**)&p_sn,   g_sn);
        cudaGetSymbolAddress((void**)&p_sn2,  g_sn2);
        cudaGetSymbolAddress((void**)&p_g1,   g_g1);
        cudaGetSymbolAddress((void**)&p_sh1,  g_sh1);
        cudaGetSymbolAddress((void**)&p_og1,  g_og1);
        cudaGetSymbolAddress((void**)&p_g2,   g_g2);
        cudaGetSymbolAddress((void**)&p_sh2,  g_sh2);
        cudaGetSymbolAddress((void**)&p_og2,  g_og2);
        cudaGetSymbolAddress((void**)&p_a1,   g_a1);
        cudaGetSymbolAddress((void**)&p_q,    g_q);
        cudaGetSymbolAddress((void**)&p_k,    g_k);
        cudaGetSymbolAddress((void**)&p_v,    g_v);
        cudaGetSymbolAddress((void**)&p_attg, g_attg);
        cudaGetSymbolAddress((void**)&p_o,    g_o);
    }

    const int M1 = NATOM;
    const int M2 = SS * NATOM;

    k_init_a<<<(SNC + 255) / 256, 256>>>(atom_single);

    for (int i = 0; i < NBLK; i++) {
        const float* gw  = aln_gate_w  + (size_t)i * CC * CC;
        const float* gb  = aln_gate_b  + (size_t)i * CC;
        const float* shw = aln_shift_w + (size_t)i * CC * CC;
        const float* qwi = q_w  + (size_t)i * CC * CC;
        const float* qbi = q_b  + (size_t)i * CC;
        const float* kwi = k_w  + (size_t)i * CC * CC;
        const float* vwi = v_w  + (size_t)i * CC * CC;
        const float* gtw = gate_w + (size_t)i * CC * CC;
        const float* otw = out_w  + (size_t)i * CC * CC;
        const float* ogw = og_w   + (size_t)i * CC * CC;
        const float* ogb = og_b   + (size_t)i * CC;
        const float* tgw = t_aln_gate_w  + (size_t)i * CC * CC;
        const float* tgb = t_aln_gate_b  + (size_t)i * CC;
        const float* tsw = t_aln_shift_w + (size_t)i * CC * CC;
        const float* taw = t_a_w   + (size_t)i * CC * 2 * CC;
        const float* tbw = t_b_w   + (size_t)i * CC * 2 * CC;
        const float* tow = t_out_w + (size_t)i * 2 * CC * CC;
        const float* togw= t_og_w  + (size_t)i * CC * CC;
        const float* togb= t_og_b  + (size_t)i * CC;

        // dual LN of s
        k_ln_s<<<NATOM, 128>>>(atom_proj,
                               aln_s_w + (size_t)i * CC,  aln_s_b + (size_t)i * CC,
                               t_aln_s_w + (size_t)i * CC, t_aln_s_b + (size_t)i * CC);

        // 6 sn projections, one launch
        {
            GB gb6;
            gb6.X[0]=p_sn;  gb6.W[0]=gw;   gb6.B[0]=gb;   gb6.Y[0]=p_g1;  gb6.epi[0]=EPI_SIG;
            gb6.X[1]=p_sn;  gb6.W[1]=shw;  gb6.B[1]=0;    gb6.Y[1]=p_sh1; gb6.epi[1]=EPI_NONE;
            gb6.X[2]=p_sn;  gb6.W[2]=ogw;  gb6.B[2]=ogb;  gb6.Y[2]=p_og1; gb6.epi[2]=EPI_SIG;
            gb6.X[3]=p_sn2; gb6.W[3]=tgw;  gb6.B[3]=tgb;  gb6.Y[3]=p_g2;  gb6.epi[3]=EPI_SIG;
            gb6.X[4]=p_sn2; gb6.W[4]=tsw;  gb6.B[4]=0;    gb6.Y[4]=p_sh2; gb6.epi[4]=EPI_NONE;
            gb6.X[5]=p_sn2; gb6.W[5]=togw; gb6.B[5]=togb; gb6.Y[5]=p_og2; gb6.epi[5]=EPI_SIG;
            gemm64b<<<dim3(M1/64, CC/64, 6), 256>>>(gb6, CC, CC);
        }

        // pair bias (independent of a1 — launch early)
        k_zb<<<(NATOM * WIN + 255) / 256, 256>>>(atom_pair,
                                                 pair_ln_w + (size_t)i * CPD,
                                                 pair_ln_b + (size_t)i * CPD,
                                                 pair_w + (size_t)i * CPD * HH);

        // a1 = g1 * LN_na(a) + sh1
        k_mod<<<dim3(NATOM, SS), 128>>>(p_g1, p_sh1, p_a1);

        // q,k,v,att-gate, one launch
        {
            GB gb4;
            gb4.X[0]=p_a1; gb4.W[0]=qwi; gb4.B[0]=qbi; gb4.Y[0]=p_q;    gb4.epi[0]=EPI_NONE;
            gb4.X[1]=p_a1; gb4.W[1]=kwi; gb4.B[1]=0;   gb4.Y[1]=p_k;    gb4.epi[1]=EPI_NONE;
            gb4.X[2]=p_a1; gb4.W[2]=vwi; gb4.B[2]=0;   gb4.Y[2]=p_v;    gb4.epi[2]=EPI_NONE;
            gb4.X[3]=p_a1; gb4.W[3]=gtw; gb4.B[3]=0;   gb4.Y[3]=p_attg; gb4.epi[3]=EPI_SIG;
            gb4.X[4]=p_a1; gb4.W[4]=qwi; gb4.B[4]=0;   gb4.Y[4]=p_q;    gb4.epi[4]=EPI_NONE;
            gb4.X[5]=p_a1; gb4.W[5]=qwi; gb4.B[5]=0;   gb4.Y[5]=p_q;    gb4.epi[5]=EPI_NONE;
            gemm64b<<<dim3(M2/64, CC/64, 4), 256>>>(gb4, CC, CC);
        }

        // attention
        k_attn<<<dim3(NQB, HH, SS), 128>>>(mask);

        // gated out-proj + residual, fused
        gemm_gateout<<<dim3(M2/64, CC/64), 256>>>(p_attg, p_o, otw, p_og1);

        // transition
        k_mod<<<dim3(NATOM, SS), 128>>>(p_g2, p_sh2, p_a1);
        gemm_dual<<<dim3(M2/64, (2*CC)/64), 256>>>(p_a1, taw, tbw);
        gemm_tout<<<dim3(M2/64, CC/64), 256>>>(tow, p_og2);
    }

    // token head
    gemm_tok<<<dim3(M2/64, CTD/64), 256>>>(tok_w);
    k_zero_out<<<(SS * TT * CTD + 255) / 256, 256>>>(out);
    k_count<<<(NATOM + 255) / 256, 256>>>(tok_idx);
    k_invcnt<<<(TT + 255) / 256, 256>>>();
    k_scatter<<<(SS * NATOM * CTD + 255) / 256, 256>>>(tok_idx, out);
}

// round 7
// speedup vs baseline: 1.8625x; 1.2399x over previous
#include <cuda_runtime.h>
#include <math.h>
#include <stdint.h>

#define SS 2
#define NATOM 2048
#define CC 128
#define HH 8
#define DHD 16
#define CPD 16
#define TT 512
#define CTD 384
#define NBLK 3
#define WIN 128
#define NQB (NATOM/32)
#define EPS 1e-5f
#define SNC (SS*NATOM*CC)

#define EPI_NONE 0
#define EPI_SIG  1

#define AP 36
#define BP 72

// ---------------- scratch ----------------
__device__ __align__(16) float g_sn  [NATOM*CC];
__device__ __align__(16) float g_sn2 [NATOM*CC];
__device__ __align__(16) float g_g1  [NATOM*CC];
__device__ __align__(16) float g_sh1 [NATOM*CC];
__device__ __align__(16) float g_og1 [NATOM*CC];
__device__ __align__(16) float g_g2  [NATOM*CC];
__device__ __align__(16) float g_sh2 [NATOM*CC];
__device__ __align__(16) float g_og2 [NATOM*CC];
__device__ __align__(16) float g_a   [SNC];
__device__ __align__(16) float g_a1  [SNC];
__device__ __align__(16) float g_q   [SNC];
__device__ __align__(16) float g_k   [SNC];
__device__ __align__(16) float g_v   [SNC];
__device__ __align__(16) float g_attg[SNC];
__device__ __align__(16) float g_o   [SNC];
__device__ __align__(16) float g_zb  [HH*NATOM*WIN];
__device__ __align__(16) float g_hid [SS*NATOM*2*CC];
__device__ __align__(16) float g_qtok[SS*NATOM*CTD];
__device__ float g_cnt[TT];

// ---------------- helpers ----------------
__device__ __forceinline__ void blockReduce2_128(float& a, float& b) {
    #pragma unroll
    for (int o = 16; o; o >>= 1) {
        a += __shfl_xor_sync(0xffffffffu, a, o);
        b += __shfl_xor_sync(0xffffffffu, b, o);
    }
    __shared__ float sa[4], sb[4];
    int w = threadIdx.x >> 5;
    if ((threadIdx.x & 31) == 0) { sa[w] = a; sb[w] = b; }
    __syncthreads();
    a = sa[0] + sa[1] + sa[2] + sa[3];
    b = sb[0] + sb[1] + sb[2] + sb[3];
}

__device__ __forceinline__ float sigf(float x) { return 1.0f / (1.0f + __expf(-x)); }

__device__ __forceinline__ unsigned f2tf(float f) {
    unsigned u; asm("cvt.rna.tf32.f32 %0, %1;" : "=r"(u) : "f"(f)); return u;
}

__device__ __forceinline__ void mma_tf32(float (&d)[4], const unsigned (&a)[4], const unsigned (&b)[2]) {
    asm volatile(
        "mma.sync.aligned.m16n8k8.row.col.f32.tf32.tf32.f32 "
        "{%0,%1,%2,%3}, {%4,%5,%6,%7}, {%8,%9}, {%0,%1,%2,%3};\n"
        : "+f"(d[0]), "+f"(d[1]), "+f"(d[2]), "+f"(d[3])
        : "r"(a[0]), "r"(a[1]), "r"(a[2]), "r"(a[3]), "r"(b[0]), "r"(b[1]));
}

// ---------------- tf32 GEMM building blocks ----------------
// CTA tile 128(M) x 64(N), K-chunk 32, 256 threads = 8 warps (4x2 of 32x32).

__device__ __forceinline__ void stageA(unsigned (*As)[AP], const float* __restrict__ X,
                                       int m0, int k0, int ld) {
    int t = threadIdx.x;
    int r = t >> 1, cb = (t & 1) * 16;
    const float4* src = reinterpret_cast<const float4*>(X + (size_t)(m0 + r) * ld + k0 + cb);
    #pragma unroll
    for (int i = 0; i < 4; i++) {
        float4 v = src[i];
        uint4 u = make_uint4(f2tf(v.x), f2tf(v.y), f2tf(v.z), f2tf(v.w));
        *reinterpret_cast<uint4*>(&As[r][cb + 4*i]) = u;
    }
}

// A = attg * o elementwise while staging
__device__ __forceinline__ void stageA_mul(unsigned (*As)[AP], const float* __restrict__ X1,
                                           const float* __restrict__ X2, int m0, int k0, int ld) {
    int t = threadIdx.x;
    int r = t >> 1, cb = (t & 1) * 16;
    size_t base = (size_t)(m0 + r) * ld + k0 + cb;
    const float4* s1 = reinterpret_cast<const float4*>(X1 + base);
    const float4* s2 = reinterpret_cast<const float4*>(X2 + base);
    #pragma unroll
    for (int i = 0; i < 4; i++) {
        float4 a = s1[i], b = s2[i];
        uint4 u = make_uint4(f2tf(a.x*b.x), f2tf(a.y*b.y), f2tf(a.z*b.z), f2tf(a.w*b.w));
        *reinterpret_cast<uint4*>(&As[r][cb + 4*i]) = u;
    }
}

__device__ __forceinline__ void stageB(unsigned (*Bs)[BP], const float* __restrict__ W,
                                       int k0, int n0, int ld) {
    int t = threadIdx.x;
    int k = t >> 3, nb = (t & 7) * 8;
    const float4* src = reinterpret_cast<const float4*>(W + (size_t)(k0 + k) * ld + n0 + nb);
    float4 v0 = src[0], v1 = src[1];
    *reinterpret_cast<uint4*>(&Bs[k][nb])     = make_uint4(f2tf(v0.x), f2tf(v0.y), f2tf(v0.z), f2tf(v0.w));
    *reinterpret_cast<uint4*>(&Bs[k][nb + 4]) = make_uint4(f2tf(v1.x), f2tf(v1.y), f2tf(v1.z), f2tf(v1.w));
}

__device__ __forceinline__ void compute32(const unsigned (*As)[AP], const unsigned (*Bs)[BP],
                                          float (*acc)[4][4], int wm, int wn, int g, int tig) {
    #pragma unroll
    for (int ks = 0; ks < 4; ks++) {
        int k8 = ks * 8;
        unsigned a[2][4], b[4][2];
        #pragma unroll
        for (int i = 0; i < 2; i++) {
            int rb = wm * 32 + i * 16;
            a[i][0] = As[rb + g    ][k8 + tig];
            a[i][1] = As[rb + g + 8][k8 + tig];
            a[i][2] = As[rb + g    ][k8 + tig + 4];
            a[i][3] = As[rb + g + 8][k8 + tig + 4];
        }
        #pragma unroll
        for (int j = 0; j < 4; j++) {
            int nb = wn * 32 + j * 8;
            b[j][0] = Bs[k8 + tig    ][nb + g];
            b[j][1] = Bs[k8 + tig + 4][nb + g];
        }
        #pragma unroll
        for (int i = 0; i < 2; i++)
            #pragma unroll
            for (int j = 0; j < 4; j++)
                mma_tf32(acc[i][j], a[i], b[j]);
    }
}

// element (m,n) of this thread's accumulators
#define EPILOGUE_LOOP(BODY)                                                    \
    _Pragma("unroll")                                                          \
    for (int i = 0; i < 2; i++) {                                              \
        _Pragma("unroll")                                                      \
        for (int j = 0; j < 4; j++) {                                          \
            _Pragma("unroll")                                                  \
            for (int r = 0; r < 4; r++) {                                      \
                int m = m0 + wm*32 + i*16 + g + ((r >> 1) ? 8 : 0);            \
                int n = n0 + wn*32 + j*8 + 2*tig + (r & 1);                    \
                BODY                                                           \
            }                                                                  \
        }                                                                      \
    }

struct GB {
    const float* X[6];
    const float* W[6];
    const float* B[6];
    float*       Y[6];
    int          epi[6];
};

// batched: z selects (X,W,B,Y,epi). Shared M (grid.x*128), Ncol, K.
__global__ void tgemm_b(GB gb, int Ncol, int K) {
    __shared__ unsigned As[128][AP];
    __shared__ unsigned Bs[32][BP];
    int z = blockIdx.z;
    const float* X = gb.X[z];
    const float* W = gb.W[z];
    int m0 = blockIdx.x * 128, n0 = blockIdx.y * 64;
    int tid = threadIdx.x, lane = tid & 31, w = tid >> 5;
    int g = lane >> 2, tig = lane & 3, wm = w >> 1, wn = w & 1;
    float acc[2][4][4] = {};
    for (int k0 = 0; k0 < K; k0 += 32) {
        stageA(As, X, m0, k0, K);
        stageB(Bs, W, k0, n0, Ncol);
        __syncthreads();
        compute32(As, Bs, acc, wm, wn, g, tig);
        __syncthreads();
    }
    const float* bias = gb.B[z];
    float* Y = gb.Y[z];
    int epi = gb.epi[z];
    EPILOGUE_LOOP({
        float v = acc[i][j][r];
        if (bias) v += bias[n];
        if (epi == EPI_SIG) v = sigf(v);
        Y[(size_t)m * Ncol + n] = v;
    })
}

// gated out-proj: A = attg*o on the fly; a += og * acc. M=SS*NATOM, N=K=128.
__global__ void tgemm_gateout(const float* __restrict__ attg, const float* __restrict__ o,
                              const float* __restrict__ Wm, const float* __restrict__ og) {
    __shared__ unsigned As[128][AP];
    __shared__ unsigned Bs[32][BP];
    int m0 = blockIdx.x * 128, n0 = blockIdx.y * 64;
    int tid = threadIdx.x, lane = tid & 31, w = tid >> 5;
    int g = lane >> 2, tig = lane & 3, wm = w >> 1, wn = w & 1;
    float acc[2][4][4] = {};
    for (int k0 = 0; k0 < CC; k0 += 32) {
        stageA_mul(As, attg, o, m0, k0, CC);
        stageB(Bs, Wm, k0, n0, CC);
        __syncthreads();
        compute32(As, Bs, acc, wm, wn, g, tig);
        __syncthreads();
    }
    EPILOGUE_LOOP({
        g_a[(size_t)m * CC + n] += og[(m & (NATOM - 1)) * CC + n] * acc[i][j][r];
    })
}

// transition dual gemm: hid = silu(X@Wa) * (X@Wb). Ncol=256, K=128.
__global__ void tgemm_dual(const float* __restrict__ X, const float* __restrict__ Wa,
                           const float* __restrict__ Wb) {
    __shared__ unsigned As[128][AP];
    __shared__ unsigned Bs[2][32][BP];
    const int N2 = 2 * CC;
    int m0 = blockIdx.x * 128, n0 = blockIdx.y * 64;
    int tid = threadIdx.x, lane = tid & 31, w = tid >> 5;
    int g = lane >> 2, tig = lane & 3, wm = w >> 1, wn = w & 1;
    float acc[2][2][4][4] = {};
    for (int k0 = 0; k0 < CC; k0 += 32) {
        stageA(As, X, m0, k0, CC);
        stageB(Bs[0], Wa, k0, n0, N2);
        stageB(Bs[1], Wb, k0, n0, N2);
        __syncthreads();
        compute32(As, Bs[0], acc[0], wm, wn, g, tig);
        compute32(As, Bs[1], acc[1], wm, wn, g, tig);
        __syncthreads();
    }
    EPILOGUE_LOOP({
        float h = acc[0][i][j][r];
        g_hid[(size_t)m * N2 + n] = h * sigf(h) * acc[1][i][j][r];
    })
}

// t_out: a += og * (hid @ W). K=256, Ncol=128.
__global__ void tgemm_tout(const float* __restrict__ Wm, const float* __restrict__ og) {
    __shared__ unsigned As[128][AP];
    __shared__ unsigned Bs[32][BP];
    const int K = 2 * CC;
    int m0 = blockIdx.x * 128, n0 = blockIdx.y * 64;
    int tid = threadIdx.x, lane = tid & 31, w = tid >> 5;
    int g = lane >> 2, tig = lane & 3, wm = w >> 1, wn = w & 1;
    float acc[2][4][4] = {};
    for (int k0 = 0; k0 < K; k0 += 32) {
        stageA(As, g_hid, m0, k0, K);
        stageB(Bs, Wm, k0, n0, CC);
        __syncthreads();
        compute32(As, Bs, acc, wm, wn, g, tig);
        __syncthreads();
    }
    EPILOGUE_LOOP({
        g_a[(size_t)m * CC + n] += og[(m & (NATOM - 1)) * CC + n] * acc[i][j][r];
    })
}

// token head: qtok = relu(a @ tok_w). Ncol=384, K=128.
__global__ void tgemm_tok(const float* __restrict__ Wm) {
    __shared__ unsigned As[128][AP];
    __shared__ unsigned Bs[32][BP];
    int m0 = blockIdx.x * 128, n0 = blockIdx.y * 64;
    int tid = threadIdx.x, lane = tid & 31, w = tid >> 5;
    int g = lane >> 2, tig = lane & 3, wm = w >> 1, wn = w & 1;
    float acc[2][4][4] = {};
    for (int k0 = 0; k0 < CC; k0 += 32) {
        stageA(As, g_a, m0, k0, CC);
        stageB(Bs, Wm, k0, n0, CTD);
        __syncthreads();
        compute32(As, Bs, acc, wm, wn, g, tig);
        __syncthreads();
    }
    EPILOGUE_LOOP({
        g_qtok[(size_t)m * CTD + n] = fmaxf(acc[i][j][r], 0.0f);
    })
}

// ---------------- LN kernels ----------------
__global__ void k_ln_s(const float* __restrict__ ap,
                       const float* __restrict__ w1, const float* __restrict__ b1,
                       const float* __restrict__ w2, const float* __restrict__ b2) {
    int n = blockIdx.x, t = threadIdx.x;
    float x = ap[n * CC + t];
    float s1 = x, s2 = x * x;
    blockReduce2_128(s1, s2);
    float mu = s1 * (1.0f / CC);
    float var = s2 * (1.0f / CC) - mu * mu;
    float xn = (x - mu) * rsqrtf(var + EPS);
    g_sn [n * CC + t] = xn * w1[t] + b1[t];
    g_sn2[n * CC + t] = xn * w2[t] + b2[t];
}

__global__ void k_mod(const float* __restrict__ gate, const float* __restrict__ shift,
                      float* __restrict__ dst) {
    int n = blockIdx.x, s = blockIdx.y, t = threadIdx.x;
    float x = g_a[(size_t)(s * NATOM + n) * CC + t];
    float s1 = x, s2 = x * x;
    blockReduce2_128(s1, s2);
    float mu = s1 * (1.0f / CC);
    float var = s2 * (1.0f / CC) - mu * mu;
    float xn = (x - mu) * rsqrtf(var + EPS);
    dst[(size_t)(s * NATOM + n) * CC + t] = gate[n * CC + t] * xn + shift[n * CC + t];
}

// ---------------- pair bias ----------------
__global__ void k_zb(const float* __restrict__ pair, const float* __restrict__ lnw,
                     const float* __restrict__ lnb, const float* __restrict__ pw) {
    int idx = blockIdx.x * blockDim.x + threadIdx.x;
    if (idx >= NATOM * WIN) return;
    int q = idx >> 7, w = idx & 127;
    int m = (q >> 5) * 32 - 48 + w;
    float out[HH];
    #pragma unroll
    for (int h = 0; h < HH; h++) out[h] = 0.0f;
    if (m >= 0 && m < NATOM) {
        const float4* p = reinterpret_cast<const float4*>(pair + ((size_t)q * NATOM + m) * CPD);
        float v[CPD];
        float s1 = 0.0f, s2 = 0.0f;
        #pragma unroll
        for (int c4 = 0; c4 < 4; c4++) {
            float4 t = p[c4];
            v[c4*4+0] = t.x; v[c4*4+1] = t.y; v[c4*4+2] = t.z; v[c4*4+3] = t.w;
        }
        #pragma unroll
        for (int c = 0; c < CPD; c++) { s1 += v[c]; s2 += v[c] * v[c]; }
        float mu = s1 * (1.0f / CPD);
        float var = s2 * (1.0f / CPD) - mu * mu;
        float r = rsqrtf(var + EPS);
        #pragma unroll
        for (int c = 0; c < CPD; c++) {
            float xn = (v[c] - mu) * r * lnw[c] + lnb[c];
            #pragma unroll
            for (int h = 0; h < HH; h++) out[h] += xn * pw[c * HH + h];
        }
    }
    #pragma unroll
    for (int h = 0; h < HH; h++)
        g_zb[((size_t)h * NATOM + q) * WIN + w] = out[h];
}

// ---------------- local attention ----------------
__global__ void k_attn(const float* __restrict__ mask) {
    int qb = blockIdx.x, h = blockIdx.y, s = blockIdx.z;
    __shared__ float qs[32][DHD];
    __shared__ float ks[WIN][DHD];
    __shared__ float vs[WIN][DHD];
    __shared__ float mb[WIN];
    int tid = threadIdx.x;
    int kbase = qb * 32 - 48;
    for (int i = tid; i < 32 * DHD; i += 128) {
        int qi = i / DHD, d = i % DHD;
        qs[qi][d] = g_q[((size_t)s * NATOM + qb * 32 + qi) * CC + h * DHD + d] * 0.25f;
    }
    for (int i = tid; i < WIN * DHD; i += 128) {
        int j = i / DHD, d = i % DHD;
        int m = kbase + j;
        float kk = 0.0f, vv = 0.0f;
        if (m >= 0 && m < NATOM) {
            kk = g_k[((size_t)s * NATOM + m) * CC + h * DHD + d];
            vv = g_v[((size_t)s * NATOM + m) * CC + h * DHD + d];
        }
        ks[j][d] = kk; vs[j][d] = vv;
    }
    for (int j = tid; j < WIN; j += 128) {
        int m = kbase + j;
        mb[j] = (m >= 0 && m < NATOM) ? (mask[m] - 1.0f) * 1e8f : -1e30f;
    }
    __syncthreads();

    int qi = tid >> 2;
    int lane = tid & 3;
    int qg = qb * 32 + qi;
    const float* zrow = g_zb + ((size_t)h * NATOM + qg) * WIN;

    float lj[32];
    float mx = -1e30f;
    #pragma unroll
    for (int jj = 0; jj < 32; jj++) {
        int j = lane + jj * 4;
        float dot = 0.0f;
        #pragma unroll
        for (int d = 0; d < DHD; d++) dot += qs[qi][d] * ks[j][d];
        float l = dot + zrow[j] + mb[j];
        lj[jj] = l;
        mx = fmaxf(mx, l);
    }
    mx = fmaxf(mx, __shfl_xor_sync(0xffffffffu, mx, 1, 4));
    mx = fmaxf(mx, __shfl_xor_sync(0xffffffffu, mx, 2, 4));

    float sum = 0.0f;
    float oacc[DHD];
    #pragma unroll
    for (int d = 0; d < DHD; d++) oacc[d] = 0.0f;
    #pragma unroll
    for (int jj = 0; jj < 32; jj++) {
        int j = lane + jj * 4;
        float p = __expf(lj[jj] - mx);
        sum += p;
        #pragma unroll
        for (int d = 0; d < DHD; d++) oacc[d] += p * vs[j][d];
    }
    sum += __shfl_xor_sync(0xffffffffu, sum, 1, 4);
    sum += __shfl_xor_sync(0xffffffffu, sum, 2, 4);
    #pragma unroll
    for (int d = 0; d < DHD; d++) {
        oacc[d] += __shfl_xor_sync(0xffffffffu, oacc[d], 1, 4);
        oacc[d] += __shfl_xor_sync(0xffffffffu, oacc[d], 2, 4);
    }
    if (lane == 0) {
        float inv = 1.0f / sum;
        #pragma unroll
        for (int d = 0; d < DHD; d++)
            g_o[((size_t)s * NATOM + qg) * CC + h * DHD + d] = oacc[d] * inv;
    }
}

// ---------------- small kernels ----------------
__global__ void k_init_a(const float* __restrict__ src) {
    int i = blockIdx.x * blockDim.x + threadIdx.x;
    if (i < SNC) g_a[i] = src[i];
}

__global__ void k_zero_out(float* __restrict__ out) {
    int i = blockIdx.x * blockDim.x + threadIdx.x;
    if (i < SS * TT * CTD) out[i] = 0.0f;
    if (i < TT) g_cnt[i] = 0.0f;
}

__global__ void k_count(const int* __restrict__ tok) {
    int n = blockIdx.x * blockDim.x + threadIdx.x;
    if (n < NATOM) atomicAdd(&g_cnt[tok[n]], 1.0f);
}

__global__ void k_invcnt() {
    int t = blockIdx.x * blockDim.x + threadIdx.x;
    if (t < TT) g_cnt[t] = 1.0f / fmaxf(g_cnt[t], 1.0f);
}

__global__ void k_scatter(const int* __restrict__ tok, float* __restrict__ out) {
    int i = blockIdx.x * blockDim.x + threadIdx.x;
    if (i >= SS * NATOM * CTD) return;
    int c = i % CTD;
    int n = (i / CTD) % NATOM;
    int s = i / (CTD * NATOM);
    int t = tok[n];
    atomicAdd(&out[((size_t)s * TT + t) * CTD + c], g_qtok[i] * g_cnt[t]);
}

// ---------------- host ----------------
extern "C" void kernel_launch(void* const* d_in, const int* in_sizes, int n_in,
                              void* d_out, int out_size) {
    const float* atom_single = (const float*)d_in[0];
    const float* atom_proj   = (const float*)d_in[1];
    const float* atom_pair   = (const float*)d_in[2];
    const float* mask        = (const float*)d_in[3];
    const int*   tok_idx     = (const int*)  d_in[4];
    const float* aln_s_w     = (const float*)d_in[5];
    const float* aln_s_b     = (const float*)d_in[6];
    const float* aln_gate_w  = (const float*)d_in[7];
    const float* aln_gate_b  = (const float*)d_in[8];
    const float* aln_shift_w = (const float*)d_in[9];
    const float* q_w         = (const float*)d_in[10];
    const float* q_b         = (const float*)d_in[11];
    const float* k_w         = (const float*)d_in[12];
    const float* v_w         = (const float*)d_in[13];
    const float* pair_ln_w   = (const float*)d_in[14];
    const float* pair_ln_b   = (const float*)d_in[15];
    const float* pair_w      = (const float*)d_in[16];
    const float* gate_w      = (const float*)d_in[17];
    const float* out_w       = (const float*)d_in[18];
    const float* og_w        = (const float*)d_in[19];
    const float* og_b        = (const float*)d_in[20];
    const float* t_aln_s_w   = (const float*)d_in[21];
    const float* t_aln_s_b   = (const float*)d_in[22];
    const float* t_aln_gate_w= (const float*)d_in[23];
    const float* t_aln_gate_b= (const float*)d_in[24];
    const float* t_aln_shift_w=(const float*)d_in[25];
    const float* t_a_w       = (const float*)d_in[26];
    const float* t_b_w       = (const float*)d_in[27];
    const float* t_out_w     = (const float*)d_in[28];
    const float* t_og_w      = (const float*)d_in[29];
    const float* t_og_b      = (const float*)d_in[30];
    const float* tok_w       = (const float*)d_in[31];
    float* out = (float*)d_out;

    static float *p_sn=0,*p_sn2=0,*p_g1=0,*p_sh1=0,*p_og1=0,*p_g2=0,*p_sh2=0,*p_og2=0;
    static float *p_a1=0,*p_q=0,*p_k=0,*p_v=0,*p_attg=0,*p_o=0;
    if (!p_sn) {
        cudaGetSymbolAddress((void**)&p_sn,   g_sn);
        cudaGetSymbolAddress((void**)&p_sn2,  g_sn2);
        cudaGetSymbolAddress((void**)&p_g1,   g_g1);
        cudaGetSymbolAddress((void**)&p_sh1,  g_sh1);
        cudaGetSymbolAddress((void**)&p_og1,  g_og1);
        cudaGetSymbolAddress((void**)&p_g2,   g_g2);
        cudaGetSymbolAddress((void**)&p_sh2,  g_sh2);
        cudaGetSymbolAddress((void**)&p_og2,  g_og2);
        cudaGetSymbolAddress((void**)&p_a1,   g_a1);
        cudaGetSymbolAddress((void**)&p_q,    g_q);
        cudaGetSymbolAddress((void**)&p_k,    g_k);
        cudaGetSymbolAddress((void**)&p_v,    g_v);
        cudaGetSymbolAddress((void**)&p_attg, g_attg);
        cudaGetSymbolAddress((void**)&p_o,    g_o);
    }

    const int M1 = NATOM;        // 2048 -> 16 m-tiles
    const int M2 = SS * NATOM;   // 4096 -> 32 m-tiles

    k_init_a<<<(SNC + 255) / 256, 256>>>(atom_single);

    for (int i = 0; i < NBLK; i++) {
        const float* gw  = aln_gate_w  + (size_t)i * CC * CC;
        const float* gb  = aln_gate_b  + (size_t)i * CC;
        const float* shw = aln_shift_w + (size_t)i * CC * CC;
        const float* qwi = q_w  + (size_t)i * CC * CC;
        const float* qbi = q_b  + (size_t)i * CC;
        const float* kwi = k_w  + (size_t)i * CC * CC;
        const float* vwi = v_w  + (size_t)i * CC * CC;
        const float* gtw = gate_w + (size_t)i * CC * CC;
        const float* otw = out_w  + (size_t)i * CC * CC;
        const float* ogw = og_w   + (size_t)i * CC * CC;
        const float* ogb = og_b   + (size_t)i * CC;
        const float* tgw = t_aln_gate_w  + (size_t)i * CC * CC;
        const float* tgb = t_aln_gate_b  + (size_t)i * CC;
        const float* tsw = t_aln_shift_w + (size_t)i * CC * CC;
        const float* taw = t_a_w   + (size_t)i * CC * 2 * CC;
        const float* tbw = t_b_w   + (size_t)i * CC * 2 * CC;
        const float* tow = t_out_w + (size_t)i * 2 * CC * CC;
        const float* togw= t_og_w  + (size_t)i * CC * CC;
        const float* togb= t_og_b  + (size_t)i * CC;

        // dual LN of s
        k_ln_s<<<NATOM, 128>>>(atom_proj,
                               aln_s_w + (size_t)i * CC,  aln_s_b + (size_t)i * CC,
                               t_aln_s_w + (size_t)i * CC, t_aln_s_b + (size_t)i * CC);

        // 6 sn projections, one launch (tf32 MMA)
        {
            GB gb6;
            gb6.X[0]=p_sn;  gb6.W[0]=gw;   gb6.B[0]=gb;   gb6.Y[0]=p_g1;  gb6.epi[0]=EPI_SIG;
            gb6.X[1]=p_sn;  gb6.W[1]=shw;  gb6.B[1]=0;    gb6.Y[1]=p_sh1; gb6.epi[1]=EPI_NONE;
            gb6.X[2]=p_sn;  gb6.W[2]=ogw;  gb6.B[2]=ogb;  gb6.Y[2]=p_og1; gb6.epi[2]=EPI_SIG;
            gb6.X[3]=p_sn2; gb6.W[3]=tgw;  gb6.B[3]=tgb;  gb6.Y[3]=p_g2;  gb6.epi[3]=EPI_SIG;
            gb6.X[4]=p_sn2; gb6.W[4]=tsw;  gb6.B[4]=0;    gb6.Y[4]=p_sh2; gb6.epi[4]=EPI_NONE;
            gb6.X[5]=p_sn2; gb6.W[5]=togw; gb6.B[5]=togb; gb6.Y[5]=p_og2; gb6.epi[5]=EPI_SIG;
            tgemm_b<<<dim3(M1/128, CC/64, 6), 256>>>(gb6, CC, CC);
        }

        // pair bias (independent — overlaps with the above)
        k_zb<<<(NATOM * WIN + 255) / 256, 256>>>(atom_pair,
                                                 pair_ln_w + (size_t)i * CPD,
                                                 pair_ln_b + (size_t)i * CPD,
                                                 pair_w + (size_t)i * CPD * HH);

        // a1 = g1 * LN_na(a) + sh1
        k_mod<<<dim3(NATOM, SS), 128>>>(p_g1, p_sh1, p_a1);

        // q,k,v,att-gate, one launch
        {
            GB gb4;
            gb4.X[0]=p_a1; gb4.W[0]=qwi; gb4.B[0]=qbi; gb4.Y[0]=p_q;    gb4.epi[0]=EPI_NONE;
            gb4.X[1]=p_a1; gb4.W[1]=kwi; gb4.B[1]=0;   gb4.Y[1]=p_k;    gb4.epi[1]=EPI_NONE;
            gb4.X[2]=p_a1; gb4.W[2]=vwi; gb4.B[2]=0;   gb4.Y[2]=p_v;    gb4.epi[2]=EPI_NONE;
            gb4.X[3]=p_a1; gb4.W[3]=gtw; gb4.B[3]=0;   gb4.Y[3]=p_attg; gb4.epi[3]=EPI_SIG;
            gb4.X[4]=p_a1; gb4.W[4]=qwi; gb4.B[4]=0;   gb4.Y[4]=p_q;    gb4.epi[4]=EPI_NONE;
            gb4.X[5]=p_a1; gb4.W[5]=qwi; gb4.B[5]=0;   gb4.Y[5]=p_q;    gb4.epi[5]=EPI_NONE;
            tgemm_b<<<dim3(M2/128, CC/64, 4), 256>>>(gb4, CC, CC);
        }

        // attention
        k_attn<<<dim3(NQB, HH, SS), 128>>>(mask);

        // gated out-proj + residual, fused
        tgemm_gateout<<<dim3(M2/128, CC/64), 256>>>(p_attg, p_o, otw, p_og1);

        // transition
        k_mod<<<dim3(NATOM, SS), 128>>>(p_g2, p_sh2, p_a1);
        tgemm_dual<<<dim3(M2/128, (2*CC)/64), 256>>>(p_a1, taw, tbw);
        tgemm_tout<<<dim3(M2/128, CC/64), 256>>>(tow, p_og2);
    }

    // token head
    tgemm_tok<<<dim3(M2/128, CTD/64), 256>>>(tok_w);
    k_zero_out<<<(SS * TT * CTD + 255) / 256, 256>>>(out);
    k_count<<<(NATOM + 255) / 256, 256>>>(tok_idx);
    k_invcnt<<<(TT + 255) / 256, 256>>>();
    k_scatter<<<(SS * NATOM * CTD + 255) / 256, 256>>>(tok_idx, out);
}